// round 13
// baseline (speedup 1.0000x reference)
#include <cuda_runtime.h>
#include <cuda_bf16.h>
#include <cstdint>
#include <math.h>

// ---------------------------------------------------------------------------
// Problem constants
// ---------------------------------------------------------------------------
#define NB_C   100000
#define DIM    64
#define BATCH  1024
#define BM     128
#define BN     128
#define NT     782                 // ceil(100000/128)
#define MT     8                   // 1024/128
#define CPAD   (NT * BN)           // 100096, pad rows zero
#define TILES  (NT * MT)           // 6256 work units
#define GRID   148
#define PITCH  72                  // smem row pitch in bf16 (144 B)

// smem layout
#define OFF_BH   0
#define OFF_BL   18432
#define OFF_A    36864
#define A_HALF   18432
#define A_BUF_SZ 36864
#define SMEM_BYTES (OFF_A + 2 * A_BUF_SZ)   // 110592

// ---------------------------------------------------------------------------
// Device scratch
// ---------------------------------------------------------------------------
__device__ __align__(256) __nv_bfloat16 g_Xh[BATCH * DIM];
__device__ __align__(256) __nv_bfloat16 g_Xl[BATCH * DIM];
__device__ float g_S  [BATCH];       // S_i = sum_c exp(t_ic - 1) (incl. 96 pad)
__device__ float g_per[BATCH];

// ---------------------------------------------------------------------------
// PTX helpers (sm_80-generic: ldmatrix / mma.sync / cp.async — legal on sm_103)
// ---------------------------------------------------------------------------
__device__ __forceinline__ uint32_t smem_u32(const void* p) {
    uint32_t a;
    asm("{ .reg .u64 t; cvta.to.shared.u64 t, %1; cvt.u32.u64 %0, t; }"
        : "=r"(a) : "l"(p));
    return a;
}
__device__ __forceinline__ void ldsm4(uint32_t& r0, uint32_t& r1,
                                      uint32_t& r2, uint32_t& r3, uint32_t addr) {
    asm volatile("ldmatrix.sync.aligned.m8n8.x4.shared.b16 {%0,%1,%2,%3}, [%4];"
        : "=r"(r0), "=r"(r1), "=r"(r2), "=r"(r3) : "r"(addr));
}
__device__ __forceinline__ void mma_bf16(float* c, const uint32_t* a,
                                         uint32_t b0, uint32_t b1) {
    asm volatile(
        "mma.sync.aligned.m16n8k16.row.col.f32.bf16.bf16.f32 "
        "{%0,%1,%2,%3}, {%4,%5,%6,%7}, {%8,%9}, {%0,%1,%2,%3};"
        : "+f"(c[0]), "+f"(c[1]), "+f"(c[2]), "+f"(c[3])
        : "r"(a[0]), "r"(a[1]), "r"(a[2]), "r"(a[3]), "r"(b0), "r"(b1));
}
// first k-step: C = 0 (no separate zeroing pass)
__device__ __forceinline__ void mma_bf16_z(float* c, const uint32_t* a,
                                           uint32_t b0, uint32_t b1) {
    asm volatile(
        "mma.sync.aligned.m16n8k16.row.col.f32.bf16.bf16.f32 "
        "{%0,%1,%2,%3}, {%4,%5,%6,%7}, {%8,%9}, {%10,%11,%12,%13};"
        : "=f"(c[0]), "=f"(c[1]), "=f"(c[2]), "=f"(c[3])
        : "r"(a[0]), "r"(a[1]), "r"(a[2]), "r"(a[3]), "r"(b0), "r"(b1),
          "f"(0.0f), "f"(0.0f), "f"(0.0f), "f"(0.0f));
}
__device__ __forceinline__ void cpasync16(uint32_t dst, const void* src) {
    asm volatile("cp.async.cg.shared.global [%0], [%1], 16;"
        :: "r"(dst), "l"(src));
}
#define CP_COMMIT() asm volatile("cp.async.commit_group;")
#define CP_WAIT1()  asm volatile("cp.async.wait_group 1;")
#define CP_WAIT0()  asm volatile("cp.async.wait_group 0;")

// ---------------------------------------------------------------------------
// K1: split xs into bf16 hi/lo, zero g_S
// ---------------------------------------------------------------------------
__global__ void prep_kernel(const float* __restrict__ xs) {
    int g = blockIdx.x * 256 + threadIdx.x;          // 0..65535
    float x = xs[g];
    __nv_bfloat16 h = __float2bfloat16(x);
    __nv_bfloat16 l = __float2bfloat16(x - __bfloat162float(h));
    g_Xh[g] = h; g_Xl[g] = l;
    if (g < BATCH) g_S[g] = 0.0f;
}

// ---------------------------------------------------------------------------
// K3 pieces
// ---------------------------------------------------------------------------
// Prefetch A tile (hi+lo) for unit tu into buffer BUF via cp.async.
__device__ __forceinline__ void prefetch_A(int tu, int buf, uint32_t sb, int tid) {
    const int mtp = tu & 7;
    const char* srcH = (const char*)(g_Xh + (size_t)mtp * BM * DIM);
    const char* srcL = (const char*)(g_Xl + (size_t)mtp * BM * DIM);
    const uint32_t ab = sb + OFF_A + (uint32_t)buf * A_BUF_SZ;
    #pragma unroll
    for (int it = 0; it < 4; ++it) {
        int g = tid + it * 256;                      // 1024 16B chunks
        int row = g >> 3, ch = g & 7;
        uint32_t doff = (uint32_t)row * (PITCH * 2) + ch * 16;
        cpasync16(ab + doff,          srcH + (size_t)g * 16);
        cpasync16(ab + A_HALF + doff, srcL + (size_t)g * 16);
    }
    CP_COMMIT();
}

// Load + normalize + split B tile (nt) from fp32 proxies into smem.
__device__ __forceinline__ void load_B(const float* __restrict__ proxies, int nt,
                                       char* sm, int wid, int lane) {
    #pragma unroll
    for (int rr = wid * 16; rr < wid * 16 + 16; ++rr) {
        int c = nt * BN + rr;
        float2 v = make_float2(0.f, 0.f);
        if (c < NB_C) v = reinterpret_cast<const float2*>(proxies)[(size_t)c * 32 + lane];
        float ss = v.x * v.x + v.y * v.y;
        #pragma unroll
        for (int off = 16; off >= 1; off >>= 1)
            ss += __shfl_xor_sync(0xffffffffu, ss, off);
        float sc = 2.0f / fmaxf(sqrtf(ss), 1e-12f);
        float a = v.x * sc, b = v.y * sc;            // pad rows: exact zeros
        __nv_bfloat16 ah = __float2bfloat16(a);
        __nv_bfloat16 al = __float2bfloat16(a - __bfloat162float(ah));
        __nv_bfloat16 bh = __float2bfloat16(b);
        __nv_bfloat16 bl = __float2bfloat16(b - __bfloat162float(bh));
        __nv_bfloat162 hv; hv.x = ah; hv.y = bh;
        __nv_bfloat162 lv; lv.x = al; lv.y = bl;
        *reinterpret_cast<__nv_bfloat162*>(sm + OFF_BH + rr * (PITCH * 2) + lane * 4) = hv;
        *reinterpret_cast<__nv_bfloat162*>(sm + OFF_BL + rr * (PITCH * 2) + lane * 4) = lv;
    }
}

// MMA for one unit into acc (exact frag math from the passing R12 kernel).
__device__ __forceinline__ void mma_unit(float (&acc)[2][8][4], uint32_t sb,
                                         uint32_t abase, uint32_t aOff, uint32_t bOff) {
    const uint32_t AHO = abase, ALO = abase + A_HALF;
    #pragma unroll
    for (int ks = 0; ks < 4; ++ks) {
        const uint32_t kb = ks * 32;
        uint32_t ah[2][4], al[2][4];
        #pragma unroll
        for (int mb = 0; mb < 2; ++mb) {
            uint32_t base = aOff + mb * 16 * (PITCH * 2) + kb;
            ldsm4(ah[mb][0], ah[mb][1], ah[mb][2], ah[mb][3], AHO + base);
            ldsm4(al[mb][0], al[mb][1], al[mb][2], al[mb][3], ALO + base);
        }
        uint32_t bh[4][4], bl[4][4];
        #pragma unroll
        for (int np = 0; np < 4; ++np) {
            uint32_t base = bOff + np * 16 * (PITCH * 2) + kb;
            ldsm4(bh[np][0], bh[np][1], bh[np][2], bh[np][3], sb + OFF_BH + base);
            ldsm4(bl[np][0], bl[np][1], bl[np][2], bl[np][3], sb + OFF_BL + base);
        }
        #pragma unroll
        for (int mb = 0; mb < 2; ++mb)
            #pragma unroll
            for (int np = 0; np < 4; ++np)
                #pragma unroll
                for (int h = 0; h < 2; ++h) {
                    int nb = np * 2 + h;
                    if (ks == 0)
                        mma_bf16_z(acc[mb][nb], ah[mb], bh[np][h * 2], bh[np][h * 2 + 1]);
                    else
                        mma_bf16(acc[mb][nb], ah[mb], bh[np][h * 2], bh[np][h * 2 + 1]);
                    mma_bf16(acc[mb][nb], ah[mb], bl[np][h * 2], bl[np][h * 2 + 1]);
                    mma_bf16(acc[mb][nb], al[mb], bh[np][h * 2], bh[np][h * 2 + 1]);
                }
    }
}

// Epilogue: exp + row sums + atomics (pad columns removed analytically in final1).
__device__ __forceinline__ void epi_unit(const float (&acc)[2][8][4], int tu,
                                         int wm, int lane) {
    const int mte = tu & 7, gq = lane >> 2;
    #pragma unroll
    for (int mb = 0; mb < 2; ++mb) {
        float sA = 0.f, sB = 0.f;
        #pragma unroll
        for (int nb = 0; nb < 8; ++nb) {
            sA += __expf(acc[mb][nb][0] - 1.0f) + __expf(acc[mb][nb][1] - 1.0f);
            sB += __expf(acc[mb][nb][2] - 1.0f) + __expf(acc[mb][nb][3] - 1.0f);
        }
        sA += __shfl_xor_sync(0xffffffffu, sA, 1);
        sA += __shfl_xor_sync(0xffffffffu, sA, 2);
        sB += __shfl_xor_sync(0xffffffffu, sB, 1);
        sB += __shfl_xor_sync(0xffffffffu, sB, 2);
        if ((lane & 3) == 0) {
            int row = mte * BM + wm + mb * 16 + gq;
            atomicAdd(&g_S[row],     sA);
            atomicAdd(&g_S[row + 8], sB);
        }
    }
}

// One unit: prefetch next A, wait current A, (re)load B on nt change, MMA.
__device__ __forceinline__ void do_unit(float (&acc)[2][8][4], int tu, int buf,
                                        int tend, int& cur_nt,
                                        const float* __restrict__ proxies,
                                        char* sm, uint32_t sb, int tid, int wid,
                                        int lane, uint32_t aOff, uint32_t bOff) {
    int tn = (tu + 1 < tend) ? tu + 1 : tu;
    prefetch_A(tn, buf ^ 1, sb, tid);
    CP_WAIT1();                       // A(tu) landed
    __syncthreads();                  // prior ldsm done; A(tu) visible to all
    int ntu = tu >> 3;
    if (ntu != cur_nt) {
        load_B(proxies, ntu, sm, wid, lane);
        cur_nt = ntu;
        __syncthreads();
    }
    mma_unit(acc, sb, sb + OFF_A + (uint32_t)buf * A_BUF_SZ, aOff, bOff);
}

// ---------------------------------------------------------------------------
// K3: persistent GEMM, double accumulators: epi(t-1) overlaps tensor-exec of t.
// ---------------------------------------------------------------------------
__global__ void __launch_bounds__(256) gemm_kernel(const float* __restrict__ proxies) {
    extern __shared__ __align__(16) char sm[];
    const uint32_t sb = smem_u32(sm);
    const int tid = threadIdx.x, wid = tid >> 5, lane = tid & 31;

    const int bid = blockIdx.x;
    const int per = TILES / GRID, rem = TILES % GRID;
    const int t0   = bid * per + (bid < rem ? bid : rem);
    const int tend = t0 + per + (bid < rem ? 1 : 0);

    const int wm = (wid & 3) * 32;    // 4 warps along M
    const int wn = (wid >> 2) * 64;   // 2 warps along N
    const int r  = lane & 7, q = lane >> 3;
    const uint32_t aOff = (uint32_t)(wm + r + (q & 1) * 8) * (PITCH * 2) + (q >> 1) * 16;
    const uint32_t bOff = (uint32_t)(wn + r + (q >> 1) * 8) * (PITCH * 2) + (q & 1) * 16;

    float accA[2][8][4], accB[2][8][4];
    int cur_nt = -1;

    prefetch_A(t0, 0, sb, tid);

    int t = t0, pend = -1;
    while (t < tend) {
        do_unit(accA, t, 0, tend, cur_nt, proxies, sm, sb, tid, wid, lane, aOff, bOff);
        if (pend >= 0) epi_unit(accB, pend, wm, lane);
        pend = t; ++t;
        if (t >= tend) { epi_unit(accA, pend, wm, lane); pend = -1; break; }
        do_unit(accB, t, 1, tend, cur_nt, proxies, sm, sb, tid, wid, lane, aOff, bOff);
        epi_unit(accA, pend, wm, lane);
        pend = t; ++t;
    }
    if (pend >= 0) epi_unit(accB, pend, wm, lane);
    CP_WAIT0();                       // drain outstanding prefetches before exit
}

// ---------------------------------------------------------------------------
// K4: per-sample loss, 1 warp/sample, fp32-exact positive term.
// per_i = log(S_i - 96*e^-1 - e^tpos) - tpos, tpos = 2*x.p_y/||p_y|| - 1.
// ---------------------------------------------------------------------------
__global__ void final1_kernel(const float* __restrict__ proxies,
                              const float* __restrict__ xs,
                              const int*   __restrict__ ysw) {
    int s    = (blockIdx.x * 256 + threadIdx.x) >> 5;   // sample 0..1023
    int lane = threadIdx.x & 31;
    unsigned bal = __ballot_sync(0xffffffffu, ysw[2 * lane + 1] != 0);
    int y = (bal == 0u) ? ysw[2 * s] : ysw[s];          // int64 vs int32

    float2 p = reinterpret_cast<const float2*>(proxies)[(size_t)y * 32 + lane];
    float2 x = reinterpret_cast<const float2*>(xs)[(size_t)s * 32 + lane];
    float ss = p.x * p.x + p.y * p.y;
    float dt = x.x * p.x + x.y * p.y;
    #pragma unroll
    for (int off = 16; off >= 1; off >>= 1) {
        ss += __shfl_xor_sync(0xffffffffu, ss, off);
        dt += __shfl_xor_sync(0xffffffffu, dt, off);
    }
    if (lane == 0) {
        float sc   = 2.0f / fmaxf(sqrtf(ss), 1e-12f);
        float tpos = dt * sc - 1.0f;
        float S = g_S[s] - (float)(CPAD - NB_C) * expf(-1.0f);
        g_per[s] = logf(S - expf(tpos)) - tpos;
    }
}

__global__ void final2_kernel(float* __restrict__ out) {
    __shared__ float red[1024];
    int i = threadIdx.x;
    red[i] = g_per[i];
    __syncthreads();
    for (int sft = 512; sft > 0; sft >>= 1) {
        if (i < sft) red[i] += red[i + sft];
        __syncthreads();
    }
    if (i == 0) out[0] = red[0] * (1.0f / 1024.0f);
}

// ---------------------------------------------------------------------------
// Launch (graph-capturable: kernel launches only)
// ---------------------------------------------------------------------------
extern "C" void kernel_launch(void* const* d_in, const int* in_sizes, int n_in,
                              void* d_out, int out_size) {
    const float* xs = nullptr; const int* ys = nullptr; const float* proxies = nullptr;
    for (int i = 0; i < n_in; ++i) {
        if      (in_sizes[i] == BATCH * DIM) xs      = (const float*)d_in[i];
        else if (in_sizes[i] == BATCH)       ys      = (const int*)d_in[i];
        else if (in_sizes[i] == NB_C * DIM)  proxies = (const float*)d_in[i];
    }
    (void)out_size;

    cudaFuncSetAttribute(gemm_kernel, cudaFuncAttributeMaxDynamicSharedMemorySize,
                         SMEM_BYTES);

    prep_kernel  <<<(BATCH * DIM) / 256, 256>>>(xs);
    gemm_kernel  <<<GRID, 256, SMEM_BYTES>>>(proxies);
    final1_kernel<<<128, 256>>>(proxies, xs, ys);
    final2_kernel<<<1, 1024>>>((float*)d_out);
}

// round 14
// speedup vs baseline: 1.1582x; 1.1582x over previous
#include <cuda_runtime.h>
#include <cuda_bf16.h>
#include <cstdint>
#include <math.h>

// ---------------------------------------------------------------------------
// Problem constants
// ---------------------------------------------------------------------------
#define NB_C   100000
#define DIM    64
#define BATCH  1024
#define BM     128
#define BN     128
#define NT     782                 // ceil(100000/128) -> one CTA per class tile
#define CPAD   (NT * BN)           // 100096, pad classes contribute exp(-1) each
#define PITCH  72                  // smem row pitch in bf16 (144 B)

// smem layout (bytes)
#define OFF_BH   0
#define OFF_BL   18432
#define OFF_A    36864
#define A_HALF   18432
#define A_BUF_SZ 36864
#define SMEM_BYTES (OFF_A + 2 * A_BUF_SZ)   // 110592 -> 2 CTAs/SM

// ---------------------------------------------------------------------------
// Device scratch
// ---------------------------------------------------------------------------
__device__ __align__(256) __nv_bfloat16 g_Xh[BATCH * DIM];
__device__ __align__(256) __nv_bfloat16 g_Xl[BATCH * DIM];
__device__ float g_S[BATCH];         // S_i = sum_c exp(t_ic - 1) (incl. 96 pad)
__device__ float g_loss;

// ---------------------------------------------------------------------------
// PTX helpers (sm_80-generic: ldmatrix / mma.sync / cp.async — legal on sm_103)
// ---------------------------------------------------------------------------
__device__ __forceinline__ uint32_t smem_u32(const void* p) {
    uint32_t a;
    asm("{ .reg .u64 t; cvta.to.shared.u64 t, %1; cvt.u32.u64 %0, t; }"
        : "=r"(a) : "l"(p));
    return a;
}
__device__ __forceinline__ void ldsm4(uint32_t* r, uint32_t addr) {
    asm volatile("ldmatrix.sync.aligned.m8n8.x4.shared.b16 {%0,%1,%2,%3}, [%4];"
        : "=r"(r[0]), "=r"(r[1]), "=r"(r[2]), "=r"(r[3]) : "r"(addr));
}
__device__ __forceinline__ void mma_bf16(float* c, const uint32_t* a,
                                         uint32_t b0, uint32_t b1) {
    asm volatile(
        "mma.sync.aligned.m16n8k16.row.col.f32.bf16.bf16.f32 "
        "{%0,%1,%2,%3}, {%4,%5,%6,%7}, {%8,%9}, {%0,%1,%2,%3};"
        : "+f"(c[0]), "+f"(c[1]), "+f"(c[2]), "+f"(c[3])
        : "r"(a[0]), "r"(a[1]), "r"(a[2]), "r"(a[3]), "r"(b0), "r"(b1));
}
__device__ __forceinline__ void mma_bf16_z(float* c, const uint32_t* a,
                                           uint32_t b0, uint32_t b1) {
    asm volatile(
        "mma.sync.aligned.m16n8k16.row.col.f32.bf16.bf16.f32 "
        "{%0,%1,%2,%3}, {%4,%5,%6,%7}, {%8,%9}, {%10,%11,%12,%13};"
        : "=f"(c[0]), "=f"(c[1]), "=f"(c[2]), "=f"(c[3])
        : "r"(a[0]), "r"(a[1]), "r"(a[2]), "r"(a[3]), "r"(b0), "r"(b1),
          "f"(0.0f), "f"(0.0f), "f"(0.0f), "f"(0.0f));
}
__device__ __forceinline__ void cpasync16(uint32_t dst, const void* src) {
    asm volatile("cp.async.cg.shared.global [%0], [%1], 16;" :: "r"(dst), "l"(src));
}
#define CP_COMMIT() asm volatile("cp.async.commit_group;")
#define CP_WAIT1()  asm volatile("cp.async.wait_group 1;")
#define CP_WAIT0()  asm volatile("cp.async.wait_group 0;")

// ---------------------------------------------------------------------------
// K1: split xs into bf16 hi/lo, zero accumulators
// ---------------------------------------------------------------------------
__global__ void prep_kernel(const float* __restrict__ xs) {
    int g = blockIdx.x * 256 + threadIdx.x;          // 0..65535
    float x = xs[g];
    __nv_bfloat16 h = __float2bfloat16(x);
    __nv_bfloat16 l = __float2bfloat16(x - __bfloat162float(h));
    g_Xh[g] = h; g_Xl[g] = l;
    if (g < BATCH) g_S[g] = 0.0f;
    if (g == 0)    g_loss = 0.0f;
}

// ---------------------------------------------------------------------------
// K2 pieces
// ---------------------------------------------------------------------------
__device__ __forceinline__ void prefetch_A(int mt, int buf, uint32_t sb, int tid) {
    const char* srcH = (const char*)(g_Xh + (size_t)mt * BM * DIM);
    const char* srcL = (const char*)(g_Xl + (size_t)mt * BM * DIM);
    const uint32_t ab = sb + OFF_A + (uint32_t)buf * A_BUF_SZ;
    #pragma unroll
    for (int it = 0; it < 4; ++it) {
        int g = tid + it * 256;                      // 1024 16B chunks per half
        int row = g >> 3, ch = g & 7;
        uint32_t doff = (uint32_t)row * (PITCH * 2) + ch * 16;
        cpasync16(ab + doff,          srcH + (size_t)g * 16);
        cpasync16(ab + A_HALF + doff, srcL + (size_t)g * 16);
    }
    CP_COMMIT();
}

// Load + normalize (x2 folded) + hi/lo split of this CTA's 128 classes.
// Each class normalized exactly once chip-wide. Pad rows: exact zeros.
__device__ __forceinline__ void load_B(const float* __restrict__ proxies, int nt,
                                       char* sm, int wid, int lane) {
    #pragma unroll
    for (int rr = wid * 16; rr < wid * 16 + 16; ++rr) {
        int c = nt * BN + rr;
        float2 v = make_float2(0.f, 0.f);
        if (c < NB_C) v = reinterpret_cast<const float2*>(proxies)[(size_t)c * 32 + lane];
        float ss = v.x * v.x + v.y * v.y;
        #pragma unroll
        for (int off = 16; off >= 1; off >>= 1)
            ss += __shfl_xor_sync(0xffffffffu, ss, off);
        float sc = 2.0f / fmaxf(sqrtf(ss), 1e-12f);
        float a = v.x * sc, b = v.y * sc;
        __nv_bfloat16 ah = __float2bfloat16(a);
        __nv_bfloat16 al = __float2bfloat16(a - __bfloat162float(ah));
        __nv_bfloat16 bh = __float2bfloat16(b);
        __nv_bfloat16 bl = __float2bfloat16(b - __bfloat162float(bh));
        __nv_bfloat162 hv; hv.x = ah; hv.y = bh;
        __nv_bfloat162 lv; lv.x = al; lv.y = bl;
        *reinterpret_cast<__nv_bfloat162*>(sm + OFF_BH + rr * (PITCH * 2) + lane * 4) = hv;
        *reinterpret_cast<__nv_bfloat162*>(sm + OFF_BL + rr * (PITCH * 2) + lane * 4) = lv;
    }
}

// ---------------------------------------------------------------------------
// K2: GEMM. One CTA per class tile nt; loops 8 m-tiles with double-buffered
// cp.async A. Single acc set, <=128 regs -> 2 CTAs/SM for natural overlap.
// ---------------------------------------------------------------------------
__global__ void __launch_bounds__(256, 2) gemm_kernel(const float* __restrict__ proxies) {
    extern __shared__ __align__(16) char sm[];
    const uint32_t sb = smem_u32(sm);
    const int tid = threadIdx.x, wid = tid >> 5, lane = tid & 31;
    const int nt = blockIdx.x;

    prefetch_A(0, 0, sb, tid);                       // in flight during load_B
    load_B(proxies, nt, sm, wid, lane);

    const int wm = (wid & 3) * 32;                   // 4 warps along M
    const int wn = (wid >> 2) * 64;                  // 2 warps along N
    const int r  = lane & 7, q = lane >> 3, gq = lane >> 2;
    const uint32_t aOff = (uint32_t)(wm + r + (q & 1) * 8) * (PITCH * 2) + (q >> 1) * 16;
    const uint32_t bOff = (uint32_t)(wn + r + (q >> 1) * 8) * (PITCH * 2) + (q & 1) * 16;

    for (int mt = 0; mt < 8; ++mt) {
        // Safe: the buffer being overwritten was last read in iter mt-1,
        // and the end-of-iteration barrier below ordered those reads.
        if (mt < 7) { prefetch_A(mt + 1, (mt + 1) & 1, sb, tid); CP_WAIT1(); }
        else        { CP_WAIT0(); }
        __syncthreads();                             // A(mt) + B visible to all

        const uint32_t abase = sb + OFF_A + (uint32_t)(mt & 1) * A_BUF_SZ;
        float acc[2][8][4];

        #pragma unroll
        for (int ks = 0; ks < 4; ++ks) {
            const uint32_t kb = ks * 32;
            uint32_t ah[2][4], al[2][4];
            #pragma unroll
            for (int mb = 0; mb < 2; ++mb) {
                uint32_t base = aOff + mb * 16 * (PITCH * 2) + kb;
                ldsm4(ah[mb], abase + base);
                ldsm4(al[mb], abase + A_HALF + base);
            }
            #pragma unroll
            for (int np = 0; np < 4; ++np) {         // short-lived B frags
                uint32_t bh[4], bl[4];
                uint32_t base = bOff + np * 16 * (PITCH * 2) + kb;
                ldsm4(bh, sb + OFF_BH + base);
                ldsm4(bl, sb + OFF_BL + base);
                #pragma unroll
                for (int h = 0; h < 2; ++h) {
                    int nb = np * 2 + h;
                    #pragma unroll
                    for (int mb = 0; mb < 2; ++mb) {
                        if (ks == 0)
                            mma_bf16_z(acc[mb][nb], ah[mb], bh[h * 2], bh[h * 2 + 1]);
                        else
                            mma_bf16(acc[mb][nb], ah[mb], bh[h * 2], bh[h * 2 + 1]);
                        mma_bf16(acc[mb][nb], ah[mb], bl[h * 2], bl[h * 2 + 1]);
                        mma_bf16(acc[mb][nb], al[mb], bh[h * 2], bh[h * 2 + 1]);
                    }
                }
            }
        }

        // Fused epilogue: exp(t-1), quad-reduce, atomic row sums.
        #pragma unroll
        for (int mb = 0; mb < 2; ++mb) {
            float sA = 0.f, sB = 0.f;
            #pragma unroll
            for (int nb = 0; nb < 8; ++nb) {
                sA += __expf(acc[mb][nb][0] - 1.0f) + __expf(acc[mb][nb][1] - 1.0f);
                sB += __expf(acc[mb][nb][2] - 1.0f) + __expf(acc[mb][nb][3] - 1.0f);
            }
            sA += __shfl_xor_sync(0xffffffffu, sA, 1);
            sA += __shfl_xor_sync(0xffffffffu, sA, 2);
            sB += __shfl_xor_sync(0xffffffffu, sB, 1);
            sB += __shfl_xor_sync(0xffffffffu, sB, 2);
            if ((lane & 3) == 0) {
                int row = mt * BM + wm + mb * 16 + gq;
                atomicAdd(&g_S[row],     sA);
                atomicAdd(&g_S[row + 8], sB);
            }
        }
        __syncthreads();   // all reads of A buf done before next iter overwrites
    }
}

// ---------------------------------------------------------------------------
// K3: per-sample loss, 1 warp/sample. Mirrors the GEMM's bf16-split product
// (xh*ph + xh*pl + xl*ph) so the positive term cancels to fp32 rounding.
// Pad classes (96) contributed exp(-1) each: removed analytically.
// ---------------------------------------------------------------------------
__global__ void final1_kernel(const float* __restrict__ proxies,
                              const float* __restrict__ xs,
                              const int*   __restrict__ ysw) {
    int s    = (blockIdx.x * 256 + threadIdx.x) >> 5;   // sample 0..1023
    int lane = threadIdx.x & 31;
    unsigned bal = __ballot_sync(0xffffffffu, ysw[2 * lane + 1] != 0);
    int y = (bal == 0u) ? ysw[2 * s] : ysw[s];          // int64 vs int32 detect

    float2 p = reinterpret_cast<const float2*>(proxies)[(size_t)y * 32 + lane];
    float2 x = reinterpret_cast<const float2*>(xs)[(size_t)s * 32 + lane];
    float ss = p.x * p.x + p.y * p.y;
    #pragma unroll
    for (int off = 16; off >= 1; off >>= 1)
        ss += __shfl_xor_sync(0xffffffffu, ss, off);
    float sc = 2.0f / fmaxf(sqrtf(ss), 1e-12f);

    float dot = 0.f;
    #pragma unroll
    for (int e = 0; e < 2; ++e) {
        float pv = (e ? p.y : p.x) * sc;
        float xv = (e ? x.y : x.x);
        float ph = __bfloat162float(__float2bfloat16(pv));
        float pl = __bfloat162float(__float2bfloat16(pv - ph));
        float xh = __bfloat162float(__float2bfloat16(xv));
        float xl = __bfloat162float(__float2bfloat16(xv - xh));
        dot += xh * ph + xh * pl + xl * ph;
    }
    #pragma unroll
    for (int off = 16; off >= 1; off >>= 1)
        dot += __shfl_xor_sync(0xffffffffu, dot, off);

    if (lane == 0) {
        float tpos = dot - 1.0f;
        float S = g_S[s] - (float)(CPAD - NB_C) * expf(-1.0f);
        float per = logf(S - expf(tpos)) - tpos;
        atomicAdd(&g_loss, per * (1.0f / 1024.0f));
    }
}

__global__ void final2_kernel(float* __restrict__ out) { out[0] = g_loss; }

// ---------------------------------------------------------------------------
// Launch (graph-capturable: kernel launches only)
// ---------------------------------------------------------------------------
extern "C" void kernel_launch(void* const* d_in, const int* in_sizes, int n_in,
                              void* d_out, int out_size) {
    const float* xs = nullptr; const int* ys = nullptr; const float* proxies = nullptr;
    for (int i = 0; i < n_in; ++i) {
        if      (in_sizes[i] == BATCH * DIM) xs      = (const float*)d_in[i];
        else if (in_sizes[i] == BATCH)       ys      = (const int*)d_in[i];
        else if (in_sizes[i] == NB_C * DIM)  proxies = (const float*)d_in[i];
    }
    (void)out_size;

    cudaFuncSetAttribute(gemm_kernel, cudaFuncAttributeMaxDynamicSharedMemorySize,
                         SMEM_BYTES);

    prep_kernel  <<<(BATCH * DIM) / 256, 256>>>(xs);
    gemm_kernel  <<<NT, 256, SMEM_BYTES>>>(proxies);
    final1_kernel<<<128, 256>>>(proxies, xs, ys);
    final2_kernel<<<1, 1>>>((float*)d_out);
}

// round 15
// speedup vs baseline: 1.2747x; 1.1005x over previous
#include <cuda_runtime.h>
#include <cuda_bf16.h>
#include <cstdint>
#include <math.h>

// ---------------------------------------------------------------------------
// Problem constants
// ---------------------------------------------------------------------------
#define NB_C   100000
#define DIM    64
#define BATCH  1024
#define BM     128
#define BN     128
#define NT     782                  // ceil(100000/128)
#define CPAD   (NT * BN)            // 100096; pad classes contribute exp(-1)
#define NBLK   (NT * 8)             // 6256 one-shot CTAs (mt fastest)
#define PITCH  72                   // smem row pitch in bf16 (144 B)
#define ROWB   (PITCH * 2)

#define NORM_BLOCKS (CPAD / 8)      // 12512 (8 warps/block, 1 row/warp)
#define PREP_BLOCKS 32              // xs conversion
#define K1_GRID (NORM_BLOCKS + PREP_BLOCKS + 1)

// smem layout for gemm (bytes)
#define OFF_A 0
#define OFF_B 18432
#define SMEM_BYTES 36864            // 2 CTAs/SM easily by smem

// ---------------------------------------------------------------------------
// Device scratch
// ---------------------------------------------------------------------------
__device__ __align__(256) __nv_bfloat16 g_Xb[BATCH * DIM];   // bf16(xs)
__device__ __align__(256) __nv_bfloat16 g_Pb[CPAD * DIM];    // bf16(2*p/||p||)
__device__ float    g_S[BATCH];     // S_i = sum_c exp(t_ic - 1) (incl. 96 pad)
__device__ unsigned g_cnt;          // gemm completion ticket

// ---------------------------------------------------------------------------
// PTX helpers (sm_80-generic: ldmatrix / mma.sync / cp.async — legal on sm_103)
// ---------------------------------------------------------------------------
__device__ __forceinline__ uint32_t smem_u32(const void* p) {
    uint32_t a;
    asm("{ .reg .u64 t; cvta.to.shared.u64 t, %1; cvt.u32.u64 %0, t; }"
        : "=r"(a) : "l"(p));
    return a;
}
__device__ __forceinline__ void ldsm4(uint32_t* r, uint32_t addr) {
    asm volatile("ldmatrix.sync.aligned.m8n8.x4.shared.b16 {%0,%1,%2,%3}, [%4];"
        : "=r"(r[0]), "=r"(r[1]), "=r"(r[2]), "=r"(r[3]) : "r"(addr));
}
__device__ __forceinline__ void mma_bf16(float* c, const uint32_t* a,
                                         uint32_t b0, uint32_t b1) {
    asm volatile(
        "mma.sync.aligned.m16n8k16.row.col.f32.bf16.bf16.f32 "
        "{%0,%1,%2,%3}, {%4,%5,%6,%7}, {%8,%9}, {%0,%1,%2,%3};"
        : "+f"(c[0]), "+f"(c[1]), "+f"(c[2]), "+f"(c[3])
        : "r"(a[0]), "r"(a[1]), "r"(a[2]), "r"(a[3]), "r"(b0), "r"(b1));
}
__device__ __forceinline__ void mma_bf16_z(float* c, const uint32_t* a,
                                           uint32_t b0, uint32_t b1) {
    asm volatile(
        "mma.sync.aligned.m16n8k16.row.col.f32.bf16.bf16.f32 "
        "{%0,%1,%2,%3}, {%4,%5,%6,%7}, {%8,%9}, {%10,%11,%12,%13};"
        : "=f"(c[0]), "=f"(c[1]), "=f"(c[2]), "=f"(c[3])
        : "r"(a[0]), "r"(a[1]), "r"(a[2]), "r"(a[3]), "r"(b0), "r"(b1),
          "f"(0.0f), "f"(0.0f), "f"(0.0f), "f"(0.0f));
}
__device__ __forceinline__ void cpasync16(uint32_t dst, const void* src) {
    asm volatile("cp.async.cg.shared.global [%0], [%1], 16;" :: "r"(dst), "l"(src));
}
#define CP_COMMIT() asm volatile("cp.async.commit_group;")
#define CP_WAIT0()  asm volatile("cp.async.wait_group 0;")

// ---------------------------------------------------------------------------
// K1: (a) normalize proxies (x2 folded) -> bf16 g_Pb, 1 warp/row;
//     (b) xs -> bf16 g_Xb; (c) zero g_S / g_cnt. One launch.
// ---------------------------------------------------------------------------
__global__ void prep_kernel(const float* __restrict__ proxies,
                            const float* __restrict__ xs) {
    const int b = blockIdx.x, tid = threadIdx.x, wid = tid >> 5, lane = tid & 31;

    if (b < NORM_BLOCKS) {
        int row = b * 8 + wid;                   // < CPAD by construction
        float2 v = make_float2(0.f, 0.f);
        if (row < NB_C) v = reinterpret_cast<const float2*>(proxies)[(size_t)row * 32 + lane];
        float ss = v.x * v.x + v.y * v.y;
        #pragma unroll
        for (int off = 16; off >= 1; off >>= 1)
            ss += __shfl_xor_sync(0xffffffffu, ss, off);
        float sc = 2.0f / fmaxf(sqrtf(ss), 1e-12f);
        __nv_bfloat162 o;
        o.x = __float2bfloat16(v.x * sc);        // pad rows: exact zeros
        o.y = __float2bfloat16(v.y * sc);
        reinterpret_cast<__nv_bfloat162*>(g_Pb)[(size_t)row * 32 + lane] = o;
    } else if (b < NORM_BLOCKS + PREP_BLOCKS) {
        int g = (b - NORM_BLOCKS) * 2048 + tid * 8;      // 8 floats/thread
        float4 v0 = reinterpret_cast<const float4*>(xs)[g / 4];
        float4 v1 = reinterpret_cast<const float4*>(xs)[g / 4 + 1];
        __nv_bfloat16 o[8] = {
            __float2bfloat16(v0.x), __float2bfloat16(v0.y),
            __float2bfloat16(v0.z), __float2bfloat16(v0.w),
            __float2bfloat16(v1.x), __float2bfloat16(v1.y),
            __float2bfloat16(v1.z), __float2bfloat16(v1.w) };
        *reinterpret_cast<uint4*>(&g_Xb[g]) = *reinterpret_cast<uint4*>(o);
    } else {
        #pragma unroll
        for (int k = 0; k < 4; ++k) g_S[tid * 4 + k] = 0.0f;
        if (tid == 0) g_cnt = 0u;
    }
}

// ---------------------------------------------------------------------------
// K2: one-shot GEMM CTAs (128x128, K=64, pure bf16 single term) + fused
// exp/row-sum epilogue. Last-finishing CTA computes the final loss.
// ---------------------------------------------------------------------------
__global__ void __launch_bounds__(256, 2) gemm_kernel(const float* __restrict__ proxies,
                                                      const float* __restrict__ xs,
                                                      const int*   __restrict__ ysw,
                                                      float*       __restrict__ out) {
    extern __shared__ __align__(16) char sm[];
    const uint32_t sb = smem_u32(sm);
    const int tid = threadIdx.x, wid = tid >> 5, lane = tid & 31;
    const int mt = blockIdx.x & 7, nt = blockIdx.x >> 3;   // mt fastest: B L2 reuse

    // -- async tile loads: A (samples) + B (classes), both bf16 row-major 128B/row
    {
        const char* srcA = (const char*)(g_Xb + (size_t)mt * BM * DIM);
        const char* srcB = (const char*)(g_Pb + (size_t)nt * BN * DIM);
        #pragma unroll
        for (int it = 0; it < 4; ++it) {
            int g = tid + it * 256;                        // 1024 16B chunks each
            int row = g >> 3, ch = g & 7;
            uint32_t doff = (uint32_t)row * ROWB + ch * 16;
            cpasync16(sb + OFF_A + doff, srcA + (size_t)g * 16);
            cpasync16(sb + OFF_B + doff, srcB + (size_t)g * 16);
        }
        CP_COMMIT();
    }

    const int wm = (wid & 3) * 32;                         // 4 warps along M
    const int wn = (wid >> 2) * 64;                        // 2 warps along N
    const int r  = lane & 7, q = lane >> 3, gq = lane >> 2;
    const uint32_t aOff = (uint32_t)(wm + r + (q & 1) * 8) * ROWB + (q >> 1) * 16;
    const uint32_t bOff = (uint32_t)(wn + r + (q >> 1) * 8) * ROWB + (q & 1) * 16;

    CP_WAIT0();
    __syncthreads();

    float acc[2][8][4];
    #pragma unroll
    for (int ks = 0; ks < 4; ++ks) {
        const uint32_t kb = ks * 32;
        uint32_t a[2][4];
        #pragma unroll
        for (int mb = 0; mb < 2; ++mb)
            ldsm4(a[mb], sb + OFF_A + aOff + mb * 16 * ROWB + kb);
        #pragma unroll
        for (int np = 0; np < 4; ++np) {
            uint32_t bfr[4];
            ldsm4(bfr, sb + OFF_B + bOff + np * 16 * ROWB + kb);
            #pragma unroll
            for (int h = 0; h < 2; ++h)
                #pragma unroll
                for (int mb = 0; mb < 2; ++mb) {
                    if (ks == 0)
                        mma_bf16_z(acc[mb][np * 2 + h], a[mb], bfr[h * 2], bfr[h * 2 + 1]);
                    else
                        mma_bf16(acc[mb][np * 2 + h], a[mb], bfr[h * 2], bfr[h * 2 + 1]);
                }
        }
    }

    // -- fused epilogue: exp(t-1), quad-reduce, atomic row sums
    #pragma unroll
    for (int mb = 0; mb < 2; ++mb) {
        float sA = 0.f, sB = 0.f;
        #pragma unroll
        for (int nb = 0; nb < 8; ++nb) {
            sA += __expf(acc[mb][nb][0] - 1.0f) + __expf(acc[mb][nb][1] - 1.0f);
            sB += __expf(acc[mb][nb][2] - 1.0f) + __expf(acc[mb][nb][3] - 1.0f);
        }
        sA += __shfl_xor_sync(0xffffffffu, sA, 1);
        sA += __shfl_xor_sync(0xffffffffu, sA, 2);
        sB += __shfl_xor_sync(0xffffffffu, sB, 1);
        sB += __shfl_xor_sync(0xffffffffu, sB, 2);
        if ((lane & 3) == 0) {
            int row = mt * BM + wm + mb * 16 + gq;
            atomicAdd(&g_S[row],     sA);
            atomicAdd(&g_S[row + 8], sB);
        }
    }

    // -- ticket: last-finishing CTA computes the loss (saves 2 launches)
    __threadfence();
    __shared__ unsigned s_ticket;
    if (tid == 0) s_ticket = atomicAdd(&g_cnt, 1u);
    __syncthreads();
    if (s_ticket != NBLK - 1) return;

    // ---- final: 1024 samples, 8 threads/sample, mirrors the bf16 product ----
    bool is64 = true;
    #pragma unroll
    for (int j = 1; j < 16; j += 2)
        if (ysw[j] != 0) is64 = false;               // int64 labels: odd words 0

    const int l8 = tid & 7, sg = tid >> 3;
    float lsum = 0.f;
    for (int k = 0; k < 32; ++k) {
        int s = k * 32 + sg;
        int y = is64 ? ysw[2 * s] : ysw[s];
        const float4* pv = reinterpret_cast<const float4*>(proxies + (size_t)y * DIM + l8 * 8);
        const float4* xv = reinterpret_cast<const float4*>(xs      + (size_t)s * DIM + l8 * 8);
        float4 p0 = pv[0], p1 = pv[1];
        float4 x0 = xv[0], x1 = xv[1];
        float ss = p0.x*p0.x + p0.y*p0.y + p0.z*p0.z + p0.w*p0.w
                 + p1.x*p1.x + p1.y*p1.y + p1.z*p1.z + p1.w*p1.w;
        ss += __shfl_xor_sync(0xffffffffu, ss, 1);
        ss += __shfl_xor_sync(0xffffffffu, ss, 2);
        ss += __shfl_xor_sync(0xffffffffu, ss, 4);
        float sc = 2.0f / fmaxf(sqrtf(ss), 1e-12f);
        float pe[8] = {p0.x, p0.y, p0.z, p0.w, p1.x, p1.y, p1.z, p1.w};
        float xe[8] = {x0.x, x0.y, x0.z, x0.w, x1.x, x1.y, x1.z, x1.w};
        float dot = 0.f;
        #pragma unroll
        for (int e = 0; e < 8; ++e) {
            float pb = __bfloat162float(__float2bfloat16(pe[e] * sc));
            float xb = __bfloat162float(__float2bfloat16(xe[e]));
            dot += pb * xb;
        }
        dot += __shfl_xor_sync(0xffffffffu, dot, 1);
        dot += __shfl_xor_sync(0xffffffffu, dot, 2);
        dot += __shfl_xor_sync(0xffffffffu, dot, 4);
        if (l8 == 0) {
            float tpos = dot - 1.0f;
            float S = g_S[s] - (float)(CPAD - NB_C) * expf(-1.0f);  // remove pads
            lsum += logf(S - expf(tpos)) - tpos;
        }
    }
    __shared__ float red[256];
    red[tid] = lsum;                                  // nonzero only for l8==0
    __syncthreads();
    for (int sft = 128; sft > 0; sft >>= 1) {
        if (tid < sft) red[tid] += red[tid + sft];
        __syncthreads();
    }
    if (tid == 0) out[0] = red[0] * (1.0f / 1024.0f);
}

// ---------------------------------------------------------------------------
// Launch: 2 kernels, graph-capturable.
// ---------------------------------------------------------------------------
extern "C" void kernel_launch(void* const* d_in, const int* in_sizes, int n_in,
                              void* d_out, int out_size) {
    const float* xs = nullptr; const int* ys = nullptr; const float* proxies = nullptr;
    for (int i = 0; i < n_in; ++i) {
        if      (in_sizes[i] == BATCH * DIM) xs      = (const float*)d_in[i];
        else if (in_sizes[i] == BATCH)       ys      = (const int*)d_in[i];
        else if (in_sizes[i] == NB_C * DIM)  proxies = (const float*)d_in[i];
    }
    (void)out_size;

    cudaFuncSetAttribute(gemm_kernel, cudaFuncAttributeMaxDynamicSharedMemorySize,
                         SMEM_BYTES);

    prep_kernel<<<K1_GRID, 256>>>(proxies, xs);
    gemm_kernel<<<NBLK, 256, SMEM_BYTES>>>(proxies, xs, ys, (float*)d_out);
}